// round 5
// baseline (speedup 1.0000x reference)
#include <cuda_runtime.h>

// ----------------------------------------------------------------------------
// RNNDecoder: 3-layer GRU (H=128), T=256, B=1024, fc head (out=2).
//
// R4: 128 CTAs x 256 threads, K-split.
//   - Thread (grp, u): u = hidden unit (owns its r,z,n gate rows), grp = K-half.
//     Each thread accumulates partial GEMV sums over 64 of the 128 K values
//     for all 8 batch rows -> 1536 FFMA2/thread/cell, 2 warps per SMSP.
//   - Cross-half reduce through smem (transposed, conflict-free ST.64/LD.64),
//     packed add via add.rn.f32x2; each group combines 4 of the 8 batch rows.
//   - Activations [k][b] in smem, broadcast LDS.128; weights pre-transposed
//     for 512B-coalesced warp LDG, double-buffered one kk-chunk ahead.
// ----------------------------------------------------------------------------

namespace {
constexpr int LAYERS = 3;
constexpr int H      = 128;
constexpr int G3     = 3 * H;
constexpr int T      = 256;
constexpr int BC     = 8;
constexpr int NTHR   = 256;
constexpr int NBLK   = 128;        // 1024 / BC
constexpr int KKH    = 16;         // float4 K-chunks per K-half
}

typedef unsigned long long ull;

// Transposed weights: [l][kkp][arr(ih,hh)][g(r,z,n)][tid] float4, where
// tid = grp*128 + u selects (unit u, K-half grp).
__device__ float4 g_wt[LAYERS * KKH * 2 * 3 * NTHR];

__global__ void prep_kernel(const float* __restrict__ wih,
                            const float* __restrict__ whh) {
  int idx = blockIdx.x * blockDim.x + threadIdx.x;
  if (idx >= LAYERS * KKH * 2 * 3 * NTHR) return;
  int t   = idx % NTHR;
  int g   = (idx / NTHR) % 3;
  int arr = (idx / (NTHR * 3)) % 2;
  int kkp = (idx / (NTHR * 6)) % KKH;
  int l   = idx / (NTHR * 6 * KKH);
  int u   = t & 127, grp = t >> 7;
  int k4  = grp * KKH + kkp;
  const float* src = (arr ? whh : wih) + (l * G3 + g * 128 + u) * H + k4 * 4;
  g_wt[idx] = *reinterpret_cast<const float4*>(src);
}

__device__ __forceinline__ void ffma2(ull& a, ull w, ull x) {
  asm("fma.rn.f32x2 %0, %1, %2, %0;" : "+l"(a) : "l"(w), "l"(x));
}
__device__ __forceinline__ void fadd2(ull& a, ull b) {
  asm("add.rn.f32x2 %0, %0, %1;" : "+l"(a) : "l"(b));
}
__device__ __forceinline__ ull dup2(float w) {
  ull r;
  asm("mov.b64 %0, {%1, %1};" : "=l"(r) : "f"(w));
  return r;
}
__device__ __forceinline__ float2 unpk(ull v) {
  float lo, hi;
  asm("mov.b64 {%0, %1}, %2;" : "=f"(lo), "=f"(hi) : "l"(v));
  return make_float2(lo, hi);
}
__device__ __forceinline__ float sigm(float x) {
  return __fdividef(1.0f, 1.0f + __expf(-x));
}
__device__ __forceinline__ float tanh_fast(float v) {
  float a = fabsf(v);
  float e = __expf(-2.0f * a);
  float r = __fdividef(1.0f - e, 1.0f + e);
  return copysignf(r, v);
}
__device__ __forceinline__ float comp(const float4& v, int e) {
  return e == 0 ? v.x : e == 1 ? v.y : e == 2 ? v.z : v.w;
}

__global__ void __launch_bounds__(NTHR, 1)
gru_kernel(const float* __restrict__ hiddens,
           const float* __restrict__ b_ih,
           const float* __restrict__ b_hh,
           const float* __restrict__ fc_w,
           const float* __restrict__ fc_b,
           float* __restrict__ out) {
  __shared__ __align__(16) float s_x[H * BC];            // [k][b]
  __shared__ __align__(16) float s_h[LAYERS * H * BC];   // [l][k][b]
  __shared__ __align__(16) ull   s_pA[12 * 128];         // grp1's q01 partials
  __shared__ __align__(16) ull   s_pB[12 * 128];         // grp0's q23 partials
  __shared__ float s_fcw[2 * H];
  __shared__ float s_fcb[2];

  const int tid = threadIdx.x;
  const int u   = tid & 127;
  const int grp = tid >> 7;
  const int b0  = blockIdx.x * BC;

  // Biases for hidden unit u (r,z biases pre-summed; n kept split).
  float brz_r[LAYERS], brz_z[LAYERS], bn_x[LAYERS], bn_h[LAYERS];
#pragma unroll
  for (int l = 0; l < LAYERS; l++) {
    brz_r[l] = b_ih[l * G3 + u]       + b_hh[l * G3 + u];
    brz_z[l] = b_ih[l * G3 + 128 + u] + b_hh[l * G3 + 128 + u];
    bn_x[l]  = b_ih[l * G3 + 256 + u];
    bn_h[l]  = b_hh[l * G3 + 256 + u];
  }
  s_fcw[tid] = fc_w[tid];
  if (tid < 2) s_fcb[tid] = fc_b[tid];

  // h init: hiddens[b][l][k] -> s_h[l][k][b]
  for (int i = tid; i < LAYERS * H * BC; i += NTHR) {
    int l = i >> 10, rem = i & 1023, k = rem >> 3, b = rem & 7;
    s_h[i] = hiddens[(b0 + b) * (LAYERS * H) + l * H + k];
  }
  for (int i = tid; i < H * BC; i += NTHR) s_x[i] = 0.0f;
  __syncthreads();

  for (int t = 0; t < T; t++) {
#pragma unroll 1
    for (int l = 0; l < LAYERS; l++) {
      const float* __restrict__  xb = s_x + grp * 512;
      const float* __restrict__  hb = s_h + l * (H * BC) + grp * 512;
      const float4* __restrict__ wp = g_wt + l * (KKH * 6 * NTHR) + tid;

      ull acc[3][2][4];
#pragma unroll
      for (int g = 0; g < 3; g++)
#pragma unroll
        for (int a = 0; a < 2; a++)
#pragma unroll
          for (int q = 0; q < 4; q++) acc[g][a][q] = 0ull;

      float4 wv[6], wn[6];
#pragma unroll
      for (int i = 0; i < 6; i++) wn[i] = wp[i * NTHR];

#pragma unroll 2
      for (int kkp = 0; kkp < KKH; kkp++) {
#pragma unroll
        for (int i = 0; i < 6; i++) {
          wv[i] = wn[i];
          wn[i] = wp[(((kkp + 1) & (KKH - 1)) * 6 + i) * NTHR];
        }
#pragma unroll
        for (int e = 0; e < 4; e++) {
          int k8 = (kkp * 4 + e) * 8;
          ulonglong2 xv0 = *reinterpret_cast<const ulonglong2*>(xb + k8);
          ulonglong2 xv1 = *reinterpret_cast<const ulonglong2*>(xb + k8 + 4);
          ulonglong2 hv0 = *reinterpret_cast<const ulonglong2*>(hb + k8);
          ulonglong2 hv1 = *reinterpret_cast<const ulonglong2*>(hb + k8 + 4);
#pragma unroll
          for (int g = 0; g < 3; g++) {
            ull dx = dup2(comp(wv[g], e));          // arr=0 (W_ih)
            ffma2(acc[g][0][0], dx, xv0.x);
            ffma2(acc[g][0][1], dx, xv0.y);
            ffma2(acc[g][0][2], dx, xv1.x);
            ffma2(acc[g][0][3], dx, xv1.y);
            ull dh = dup2(comp(wv[3 + g], e));      // arr=1 (W_hh)
            ffma2(acc[g][1][0], dh, hv0.x);
            ffma2(acc[g][1][1], dh, hv0.y);
            ffma2(acc[g][1][2], dh, hv1.x);
            ffma2(acc[g][1][3], dh, hv1.y);
          }
        }
      }

      // Exchange partials: each group stores the batch-half it does NOT
      // combine; transposed [i][u] -> conflict-free ST.64 across lanes.
      {
        ull* dst = grp ? s_pA : s_pB;
        int qb = grp ? 0 : 2;     // grp1 gives q01 (combined by grp0-side? no:
                                  // grp0 combines q01 -> needs grp1's q01 = s_pA)
#pragma unroll
        for (int g = 0; g < 3; g++)
#pragma unroll
          for (int a = 0; a < 2; a++)
#pragma unroll
            for (int qq = 0; qq < 2; qq++)
              dst[((g * 2 + a) * 2 + qq) * 128 + u] = acc[g][a][qb + qq];
      }
      __syncthreads();

      // Combine: grp0 -> batches 0..3 (q01), grp1 -> batches 4..7 (q23).
      {
        const ull* src = grp ? s_pB : s_pA;
        int qm = grp * 2;
#pragma unroll
        for (int g = 0; g < 3; g++)
#pragma unroll
          for (int a = 0; a < 2; a++)
#pragma unroll
            for (int qq = 0; qq < 2; qq++)
              fadd2(acc[g][a][qm + qq], src[((g * 2 + a) * 2 + qq) * 128 + u]);

        float4 hp4 = *reinterpret_cast<const float4*>(
            s_h + l * (H * BC) + u * 8 + grp * 4);
        float hp[4] = {hp4.x, hp4.y, hp4.z, hp4.w};
        float hv[4];
#pragma unroll
        for (int qq = 0; qq < 2; qq++) {
          int q = qm + qq;
          float2 xr = unpk(acc[0][0][q]), hr = unpk(acc[0][1][q]);
          float2 xz = unpk(acc[1][0][q]), hz = unpk(acc[1][1][q]);
          float2 xn = unpk(acc[2][0][q]), hn = unpk(acc[2][1][q]);
          {
            float r = sigm(xr.x + hr.x + brz_r[l]);
            float z = sigm(xz.x + hz.x + brz_z[l]);
            float n = tanh_fast(xn.x + bn_x[l] + r * (hn.x + bn_h[l]));
            hv[qq * 2 + 0] = fmaf(z, hp[qq * 2 + 0] - n, n);
          }
          {
            float r = sigm(xr.y + hr.y + brz_r[l]);
            float z = sigm(xz.y + hz.y + brz_z[l]);
            float n = tanh_fast(xn.y + bn_x[l] + r * (hn.y + bn_h[l]));
            hv[qq * 2 + 1] = fmaf(z, hp[qq * 2 + 1] - n, n);
          }
        }
        float4 o = make_float4(hv[0], hv[1], hv[2], hv[3]);
        *reinterpret_cast<float4*>(s_h + l * (H * BC) + u * 8 + grp * 4) = o;
        *reinterpret_cast<float4*>(s_x + u * 8 + grp * 4) = o;
      }
      __syncthreads();

      // fc head on top-layer output: 16 outputs (2 out x 8 batch) x 16 lanes.
      if (l == 2) {
        int oid = tid >> 4, s = tid & 15;
        int o = oid & 1, b = oid >> 1;
        float p = 0.0f;
#pragma unroll
        for (int m = 0; m < 8; m++)
          p = fmaf(s_fcw[o * H + s * 8 + m], s_x[(s * 8 + m) * 8 + b], p);
        p += __shfl_down_sync(0xffffffffu, p, 8, 16);
        p += __shfl_down_sync(0xffffffffu, p, 4, 16);
        p += __shfl_down_sync(0xffffffffu, p, 2, 16);
        p += __shfl_down_sync(0xffffffffu, p, 1, 16);
        if (s == 0) out[((b0 + b) * T + t) * 2 + o] = p + s_fcb[o];
      }
      // fc reads of s_x finish before the next cell's combine rewrites s_x:
      // that rewrite sits behind the next cell's post-gemv __syncthreads().
    }
  }
}

extern "C" void kernel_launch(void* const* d_in, const int* in_sizes, int n_in,
                              void* d_out, int out_size) {
  (void)in_sizes; (void)n_in; (void)out_size;
  const float* hiddens = (const float*)d_in[0];
  const float* W_ih    = (const float*)d_in[1];
  const float* W_hh    = (const float*)d_in[2];
  const float* b_ih    = (const float*)d_in[3];
  const float* b_hh    = (const float*)d_in[4];
  const float* fc_w    = (const float*)d_in[5];
  const float* fc_b    = (const float*)d_in[6];
  float* out = (float*)d_out;

  const int prep_elems = LAYERS * KKH * 2 * 3 * NTHR;
  prep_kernel<<<(prep_elems + 255) / 256, 256>>>(W_ih, W_hh);
  gru_kernel<<<NBLK, NTHR>>>(hiddens, b_ih, b_hh, fc_w, fc_b, out);
}

// round 6
// speedup vs baseline: 1.7283x; 1.7283x over previous
#include <cuda_runtime.h>

// ----------------------------------------------------------------------------
// RNNDecoder: 3-layer GRU (H=128), T=256, B=1024, fc head (out=2).
//
// R5 = R4 (K-split, 128 CTAs x 256 threads) with the local-memory spill fixed:
// all accumulator indices are compile-time constants (templated exchange /
// combine), keeping acc[3][2][4] in registers.
//   - Thread (grp,u): u = hidden unit (owns r,z,n rows), grp = K-half.
//   - 1536 FFMA2/thread/cell, 2 warps per SMSP -> latency co-hidden.
//   - Cross-half reduce via smem (conflict-free ST.64/LD.64) + add.rn.f32x2;
//     grp0 combines batches 0..3, grp1 combines 4..7.
//   - Weights pre-transposed for 512B-coalesced warp LDG, double-buffered.
// ----------------------------------------------------------------------------

namespace {
constexpr int LAYERS = 3;
constexpr int H      = 128;
constexpr int G3     = 3 * H;
constexpr int T      = 256;
constexpr int BC     = 8;
constexpr int NTHR   = 256;
constexpr int NBLK   = 128;        // 1024 / BC
constexpr int KKH    = 16;         // float4 K-chunks per K-half
}

typedef unsigned long long ull;

// Transposed weights: [l][kkp][arr(ih,hh)][g(r,z,n)][tid] float4,
// tid = grp*128 + u -> (unit u, K-half grp).
__device__ float4 g_wt[LAYERS * KKH * 2 * 3 * NTHR];

__global__ void prep_kernel(const float* __restrict__ wih,
                            const float* __restrict__ whh) {
  int idx = blockIdx.x * blockDim.x + threadIdx.x;
  if (idx >= LAYERS * KKH * 2 * 3 * NTHR) return;
  int t   = idx % NTHR;
  int g   = (idx / NTHR) % 3;
  int arr = (idx / (NTHR * 3)) % 2;
  int kkp = (idx / (NTHR * 6)) % KKH;
  int l   = idx / (NTHR * 6 * KKH);
  int u   = t & 127, grp = t >> 7;
  int k4  = grp * KKH + kkp;
  const float* src = (arr ? whh : wih) + (l * G3 + g * 128 + u) * H + k4 * 4;
  g_wt[idx] = *reinterpret_cast<const float4*>(src);
}

__device__ __forceinline__ void ffma2(ull& a, ull w, ull x) {
  asm("fma.rn.f32x2 %0, %1, %2, %0;" : "+l"(a) : "l"(w), "l"(x));
}
__device__ __forceinline__ void fadd2(ull& a, ull b) {
  asm("add.rn.f32x2 %0, %0, %1;" : "+l"(a) : "l"(b));
}
__device__ __forceinline__ ull dup2(float w) {
  ull r;
  asm("mov.b64 %0, {%1, %1};" : "=l"(r) : "f"(w));
  return r;
}
__device__ __forceinline__ float2 unpk(ull v) {
  float lo, hi;
  asm("mov.b64 {%0, %1}, %2;" : "=f"(lo), "=f"(hi) : "l"(v));
  return make_float2(lo, hi);
}
__device__ __forceinline__ float sigm(float x) {
  return __fdividef(1.0f, 1.0f + __expf(-x));
}
__device__ __forceinline__ float tanh_fast(float v) {
  float a = fabsf(v);
  float e = __expf(-2.0f * a);
  float r = __fdividef(1.0f - e, 1.0f + e);
  return copysignf(r, v);
}
__device__ __forceinline__ float comp(const float4& v, int e) {
  return e == 0 ? v.x : e == 1 ? v.y : e == 2 ? v.z : v.w;
}

// Store this group's partials for the batch-half the OTHER group combines.
// QB is a compile-time base so acc indices stay literal (no local spill).
template <int QB>
__device__ __forceinline__ void store_partials(ull* __restrict__ dst,
                                               const ull (&acc)[3][2][4],
                                               int u) {
#pragma unroll
  for (int g = 0; g < 3; g++)
#pragma unroll
    for (int a = 0; a < 2; a++)
#pragma unroll
      for (int qq = 0; qq < 2; qq++)
        dst[((g * 2 + a) * 2 + qq) * 128 + u] = acc[g][a][QB + qq];
}

// Add partner partials and do the GRU gate combine for this group's
// batch-half. QM/GRP compile-time -> constant acc indices, constant offsets.
template <int QM, int GRP>
__device__ __forceinline__ void combine_half(ull (&acc)[3][2][4],
                                             const ull* __restrict__ src,
                                             int u,
                                             float brz_r, float brz_z,
                                             float bn_x, float bn_h,
                                             float* __restrict__ hl,
                                             float* __restrict__ sx) {
#pragma unroll
  for (int g = 0; g < 3; g++)
#pragma unroll
    for (int a = 0; a < 2; a++)
#pragma unroll
      for (int qq = 0; qq < 2; qq++)
        fadd2(acc[g][a][QM + qq], src[((g * 2 + a) * 2 + qq) * 128 + u]);

  float4 hp4 = *reinterpret_cast<const float4*>(hl + u * 8 + GRP * 4);
  float hp[4] = {hp4.x, hp4.y, hp4.z, hp4.w};
  float hv[4];
#pragma unroll
  for (int qq = 0; qq < 2; qq++) {
    float2 xr = unpk(acc[0][0][QM + qq]), hr = unpk(acc[0][1][QM + qq]);
    float2 xz = unpk(acc[1][0][QM + qq]), hz = unpk(acc[1][1][QM + qq]);
    float2 xn = unpk(acc[2][0][QM + qq]), hn = unpk(acc[2][1][QM + qq]);
    {
      float r = sigm(xr.x + hr.x + brz_r);
      float z = sigm(xz.x + hz.x + brz_z);
      float n = tanh_fast(xn.x + bn_x + r * (hn.x + bn_h));
      hv[qq * 2 + 0] = fmaf(z, hp[qq * 2 + 0] - n, n);
    }
    {
      float r = sigm(xr.y + hr.y + brz_r);
      float z = sigm(xz.y + hz.y + brz_z);
      float n = tanh_fast(xn.y + bn_x + r * (hn.y + bn_h));
      hv[qq * 2 + 1] = fmaf(z, hp[qq * 2 + 1] - n, n);
    }
  }
  float4 o = make_float4(hv[0], hv[1], hv[2], hv[3]);
  *reinterpret_cast<float4*>(hl + u * 8 + GRP * 4) = o;
  *reinterpret_cast<float4*>(sx + u * 8 + GRP * 4) = o;
}

__global__ void __launch_bounds__(NTHR, 1)
gru_kernel(const float* __restrict__ hiddens,
           const float* __restrict__ b_ih,
           const float* __restrict__ b_hh,
           const float* __restrict__ fc_w,
           const float* __restrict__ fc_b,
           float* __restrict__ out) {
  __shared__ __align__(16) float s_x[H * BC];            // [k][b]
  __shared__ __align__(16) float s_h[LAYERS * H * BC];   // [l][k][b]
  __shared__ __align__(16) ull   s_pA[12 * 128];         // grp1's q01 partials
  __shared__ __align__(16) ull   s_pB[12 * 128];         // grp0's q23 partials
  __shared__ float s_fcw[2 * H];
  __shared__ float s_fcb[2];

  const int tid = threadIdx.x;
  const int u   = tid & 127;
  const int grp = tid >> 7;
  const int b0  = blockIdx.x * BC;

  // Biases for hidden unit u (r,z summed; n split).
  float brz_r[LAYERS], brz_z[LAYERS], bn_x[LAYERS], bn_h[LAYERS];
#pragma unroll
  for (int l = 0; l < LAYERS; l++) {
    brz_r[l] = b_ih[l * G3 + u]       + b_hh[l * G3 + u];
    brz_z[l] = b_ih[l * G3 + 128 + u] + b_hh[l * G3 + 128 + u];
    bn_x[l]  = b_ih[l * G3 + 256 + u];
    bn_h[l]  = b_hh[l * G3 + 256 + u];
  }
  s_fcw[tid] = fc_w[tid];
  if (tid < 2) s_fcb[tid] = fc_b[tid];

  // h init: hiddens[b][l][k] -> s_h[l][k][b]
  for (int i = tid; i < LAYERS * H * BC; i += NTHR) {
    int l = i >> 10, rem = i & 1023, k = rem >> 3, b = rem & 7;
    s_h[i] = hiddens[(b0 + b) * (LAYERS * H) + l * H + k];
  }
  for (int i = tid; i < H * BC; i += NTHR) s_x[i] = 0.0f;
  __syncthreads();

  for (int t = 0; t < T; t++) {
#pragma unroll 1
    for (int l = 0; l < LAYERS; l++) {
      const float* __restrict__  xb = s_x + grp * 512;
      float* __restrict__        hl = s_h + l * (H * BC);
      const float* __restrict__  hb = hl + grp * 512;
      const float4* __restrict__ wp = g_wt + l * (KKH * 6 * NTHR) + tid;

      ull acc[3][2][4];
#pragma unroll
      for (int g = 0; g < 3; g++)
#pragma unroll
        for (int a = 0; a < 2; a++)
#pragma unroll
          for (int q = 0; q < 4; q++) acc[g][a][q] = 0ull;

      float4 wv[6], wn[6];
#pragma unroll
      for (int i = 0; i < 6; i++) wn[i] = wp[i * NTHR];

#pragma unroll 2
      for (int kkp = 0; kkp < KKH; kkp++) {
#pragma unroll
        for (int i = 0; i < 6; i++) {
          wv[i] = wn[i];
          wn[i] = wp[(((kkp + 1) & (KKH - 1)) * 6 + i) * NTHR];
        }
#pragma unroll
        for (int e = 0; e < 4; e++) {
          int k8 = (kkp * 4 + e) * 8;
          ulonglong2 xv0 = *reinterpret_cast<const ulonglong2*>(xb + k8);
          ulonglong2 xv1 = *reinterpret_cast<const ulonglong2*>(xb + k8 + 4);
          ulonglong2 hv0 = *reinterpret_cast<const ulonglong2*>(hb + k8);
          ulonglong2 hv1 = *reinterpret_cast<const ulonglong2*>(hb + k8 + 4);
#pragma unroll
          for (int g = 0; g < 3; g++) {
            ull dx = dup2(comp(wv[g], e));          // W_ih
            ffma2(acc[g][0][0], dx, xv0.x);
            ffma2(acc[g][0][1], dx, xv0.y);
            ffma2(acc[g][0][2], dx, xv1.x);
            ffma2(acc[g][0][3], dx, xv1.y);
            ull dh = dup2(comp(wv[3 + g], e));      // W_hh
            ffma2(acc[g][1][0], dh, hv0.x);
            ffma2(acc[g][1][1], dh, hv0.y);
            ffma2(acc[g][1][2], dh, hv1.x);
            ffma2(acc[g][1][3], dh, hv1.y);
          }
        }
      }

      // Exchange: grp0 gives q23 (for grp1), grp1 gives q01 (for grp0).
      if (grp == 0) store_partials<2>(s_pB, acc, u);
      else          store_partials<0>(s_pA, acc, u);
      __syncthreads();

      if (grp == 0)
        combine_half<0, 0>(acc, s_pA, u, brz_r[l], brz_z[l], bn_x[l], bn_h[l],
                           hl, s_x);
      else
        combine_half<2, 1>(acc, s_pB, u, brz_r[l], brz_z[l], bn_x[l], bn_h[l],
                           hl, s_x);
      __syncthreads();

      // fc head on top-layer output: 16 outputs (2 out x 8 batch) x 16 lanes.
      if (l == 2) {
        int oid = tid >> 4, s = tid & 15;
        int o = oid & 1, b = oid >> 1;
        float p = 0.0f;
#pragma unroll
        for (int m = 0; m < 8; m++)
          p = fmaf(s_fcw[o * H + s * 8 + m], s_x[(s * 8 + m) * 8 + b], p);
        p += __shfl_down_sync(0xffffffffu, p, 8, 16);
        p += __shfl_down_sync(0xffffffffu, p, 4, 16);
        p += __shfl_down_sync(0xffffffffu, p, 2, 16);
        p += __shfl_down_sync(0xffffffffu, p, 1, 16);
        if (s == 0) out[((b0 + b) * T + t) * 2 + o] = p + s_fcb[o];
      }
      // fc reads of s_x complete before the next cell's combine rewrites s_x
      // (that rewrite is behind the next cell's post-gemv __syncthreads()).
    }
  }
}

extern "C" void kernel_launch(void* const* d_in, const int* in_sizes, int n_in,
                              void* d_out, int out_size) {
  (void)in_sizes; (void)n_in; (void)out_size;
  const float* hiddens = (const float*)d_in[0];
  const float* W_ih    = (const float*)d_in[1];
  const float* W_hh    = (const float*)d_in[2];
  const float* b_ih    = (const float*)d_in[3];
  const float* b_hh    = (const float*)d_in[4];
  const float* fc_w    = (const float*)d_in[5];
  const float* fc_b    = (const float*)d_in[6];
  float* out = (float*)d_out;

  const int prep_elems = LAYERS * KKH * 2 * 3 * NTHR;
  prep_kernel<<<(prep_elems + 255) / 256, 256>>>(W_ih, W_hh);
  gru_kernel<<<NBLK, NTHR>>>(hiddens, b_ih, b_hh, fc_w, fc_b, out);
}